// round 4
// baseline (speedup 1.0000x reference)
#include <cuda_runtime.h>
#include <cstdint>

// Problem dims (fixed by dataset): N=262144 rows, d_in=1024, d_hid=256, 128 bags.
#define NROWS_MAX 262144
#define DIN 1024
#define DHID 256
#define STAT_BLOCKS 512
#define NEG_INF_F (__int_as_float(0xff800000))

// Scratch (allocation-free rule: __device__ globals)
__device__ float     g_h[(size_t)NROWS_MAX * DHID];   // 256 MB: post-GEMM activations
__device__ float     g_scores[NROWS_MAX];
__device__ float     g_psum[STAT_BLOCKS * DHID];
__device__ float     g_psumsq[STAT_BLOCKS * DHID];
__device__ float     g_bn_a[DHID];                    // gamma * rstd
__device__ float     g_bn_c[DHID];                    // beta - mean * gamma * rstd
__device__ long long g_off[1025];                     // bag offsets (cumsum)

// Packed fp32x2 FMA (sm_100+): doubles FFMA throughput vs 3-reg FFMA (rt 2 -> effective 1)
__device__ __forceinline__ unsigned long long fma2(unsigned long long a,
                                                   unsigned long long b,
                                                   unsigned long long c) {
    unsigned long long d;
    asm("fma.rn.f32x2 %0, %1, %2, %3;" : "=l"(d) : "l"(a), "l"(b), "l"(c));
    return d;
}

// ---------------------------------------------------------------------------
// Kernel 1: h = features @ W1 + b1   (SGEMM 128x128x8, f32x2 inner product)
// A: [N, 1024] row-major, B: [1024, 256] row-major, C -> g_h [N, 256]
// Grid: (256/128=2, N/128). 256 threads, 8x8 per-thread tile.
// A is stored in smem with each value DUPLICATED (pairs) so the MAC loop is
// pure fma.rn.f32x2: acc pairs cover 2 adjacent output columns.
// ---------------------------------------------------------------------------
__global__ __launch_bounds__(256, 2)
void sgemm_kernel(const float* __restrict__ A, const float* __restrict__ B,
                  const float* __restrict__ bias, int nrows)
{
    __shared__ __align__(16) float As[8][256];  // [k][2*row], value duplicated
    __shared__ __align__(16) float Bs[8][128];  // [k][col]

    const int tid  = threadIdx.x;
    const int row0 = blockIdx.y * 128;
    const int col0 = blockIdx.x * 128;

    // global load mapping
    const int arow = tid >> 1;             // 0..127
    const int akq  = (tid & 1) << 2;       // 0 or 4  (k offset within tile)
    const int brow = tid >> 5;             // 0..7
    const int bcol = (tid & 31) << 2;      // 0..124

    // compute mapping: 16x16 thread grid, 8x8 outputs each
    const int tx = tid & 15;
    const int ty = tid >> 4;

    unsigned long long acc[8][4];
    #pragma unroll
    for (int i = 0; i < 8; i++)
        #pragma unroll
        for (int j = 0; j < 4; j++) acc[i][j] = 0ull;

    const float* Aptr = A + (size_t)(row0 + arow) * DIN + akq;
    const float* Bptr = B + (size_t)brow * DHID + col0 + bcol;

    // preload tile 0
    float4 a4 = *(const float4*)(Aptr);
    float4 b4 = *(const float4*)(Bptr);
    *(float2*)&As[akq + 0][2 * arow] = make_float2(a4.x, a4.x);
    *(float2*)&As[akq + 1][2 * arow] = make_float2(a4.y, a4.y);
    *(float2*)&As[akq + 2][2 * arow] = make_float2(a4.z, a4.z);
    *(float2*)&As[akq + 3][2 * arow] = make_float2(a4.w, a4.w);
    *(float4*)&Bs[brow][bcol] = b4;
    __syncthreads();

    const int KT = DIN / 8;  // 128 k-tiles
    for (int kt = 1; kt <= KT; ++kt) {
        float4 a4n, b4n;
        if (kt < KT) {
            a4n = *(const float4*)(Aptr + kt * 8);
            b4n = *(const float4*)(Bptr + (size_t)kt * 8 * DHID);
        }
        #pragma unroll
        for (int kk = 0; kk < 8; ++kk) {
            unsigned long long ap[8], bp[4];
            #pragma unroll
            for (int i = 0; i < 8; i++)
                ap[i] = *(const unsigned long long*)&As[kk][2 * (ty * 8 + i)];
            #pragma unroll
            for (int j = 0; j < 4; j++)
                bp[j] = *(const unsigned long long*)&Bs[kk][tx * 8 + 2 * j];
            #pragma unroll
            for (int i = 0; i < 8; i++)
                #pragma unroll
                for (int j = 0; j < 4; j++)
                    acc[i][j] = fma2(ap[i], bp[j], acc[i][j]);
        }
        __syncthreads();
        if (kt < KT) {
            *(float2*)&As[akq + 0][2 * arow] = make_float2(a4n.x, a4n.x);
            *(float2*)&As[akq + 1][2 * arow] = make_float2(a4n.y, a4n.y);
            *(float2*)&As[akq + 2][2 * arow] = make_float2(a4n.z, a4n.z);
            *(float2*)&As[akq + 3][2 * arow] = make_float2(a4n.w, a4n.w);
            *(float4*)&Bs[brow][bcol] = b4n;
            __syncthreads();
        }
    }

    // epilogue: unpack, add bias, store to g_h
    #pragma unroll
    for (int i = 0; i < 8; i++) {
        int gr = row0 + ty * 8 + i;
        if (gr < nrows) {
            #pragma unroll
            for (int j = 0; j < 4; j++) {
                int gc = col0 + tx * 8 + 2 * j;
                float lo = __uint_as_float((unsigned)(acc[i][j] & 0xffffffffull));
                float hi = __uint_as_float((unsigned)(acc[i][j] >> 32));
                float2 v = make_float2(lo + __ldg(&bias[gc]),
                                       hi + __ldg(&bias[gc + 1]));
                *(float2*)&g_h[(size_t)gr * DHID + gc] = v;
            }
        }
    }
}

// ---------------------------------------------------------------------------
// Kernel 2: per-column partial sums / sumsq of g_h (coalesced, deterministic)
// Grid: STAT_BLOCKS blocks x 256 threads; thread t owns column t.
// ---------------------------------------------------------------------------
__global__ __launch_bounds__(256)
void stats_partial_kernel(int nrows)
{
    const int c = threadIdx.x;               // column 0..255
    const int b = blockIdx.x;
    const int rows_per = (nrows + gridDim.x - 1) / gridDim.x;
    const int r0 = b * rows_per;
    int r1 = r0 + rows_per;
    if (r1 > nrows) r1 = nrows;
    float s = 0.f, q = 0.f;
    for (int r = r0; r < r1; ++r) {
        float v = g_h[(size_t)r * DHID + c];
        s += v;
        q = fmaf(v, v, q);
    }
    g_psum[b * DHID + c]   = s;
    g_psumsq[b * DHID + c] = q;
}

// Kernel 3: finalize BN coefficients. 1 block x 256 threads, fixed order.
__global__ __launch_bounds__(256)
void stats_final_kernel(const float* __restrict__ gamma,
                        const float* __restrict__ beta, int nrows)
{
    const int c = threadIdx.x;
    float s = 0.f, q = 0.f;
    for (int b = 0; b < STAT_BLOCKS; ++b) {
        s += g_psum[b * DHID + c];
        q += g_psumsq[b * DHID + c];
    }
    float inv_n = 1.0f / (float)nrows;
    float mean  = s * inv_n;
    float var   = fmaf(-mean, mean, q * inv_n);   // E[x^2] - mean^2 (biased)
    float rstd  = rsqrtf(var + 1e-5f);
    float a     = gamma[c] * rstd;
    g_bn_a[c] = a;
    g_bn_c[c] = fmaf(-mean, a, beta[c]);
}

// ---------------------------------------------------------------------------
// Kernel 4: scores[r] = sum_c relu(a_c*h + c_c) * W2_c + b2.  Warp per row.
// ---------------------------------------------------------------------------
__global__ __launch_bounds__(256)
void scores_kernel(const float* __restrict__ W2, const float* __restrict__ b2,
                   int nrows)
{
    __shared__ float sa[DHID], sc[DHID], sw[DHID];
    const int tid = threadIdx.x;
    sa[tid] = g_bn_a[tid];
    sc[tid] = g_bn_c[tid];
    sw[tid] = W2[tid];
    __syncthreads();

    const int warp = tid >> 5;
    const int lane = tid & 31;
    const int row  = blockIdx.x * 8 + warp;
    if (row >= nrows) return;

    const float* hr = g_h + (size_t)row * DHID;
    float acc = 0.f;
    #pragma unroll
    for (int part = 0; part < 2; ++part) {
        int c0 = part * 128 + lane * 4;
        float4 v = *(const float4*)(hr + c0);
        acc += fmaxf(fmaf(sa[c0 + 0], v.x, sc[c0 + 0]), 0.f) * sw[c0 + 0];
        acc += fmaxf(fmaf(sa[c0 + 1], v.y, sc[c0 + 1]), 0.f) * sw[c0 + 1];
        acc += fmaxf(fmaf(sa[c0 + 2], v.z, sc[c0 + 2]), 0.f) * sw[c0 + 2];
        acc += fmaxf(fmaf(sa[c0 + 3], v.w, sc[c0 + 3]), 0.f) * sw[c0 + 3];
    }
    #pragma unroll
    for (int o = 16; o; o >>= 1) acc += __shfl_xor_sync(0xffffffffu, acc, o);
    if (lane == 0) g_scores[row] = acc + b2[0];
}

// Kernel 5: bag offsets (serial cumsum, 128 elements — trivial).
// NOTE: bag_sizes arrives as int32 (harness dtype convention; JAX x64 off).
__global__ void offsets_kernel(const int* __restrict__ bag_sizes, int n_bags)
{
    if (threadIdx.x == 0 && blockIdx.x == 0) {
        long long a = 0;
        g_off[0] = 0;
        for (int b = 0; b < n_bags; ++b) { a += (long long)bag_sizes[b]; g_off[b + 1] = a; }
    }
}

// ---------------------------------------------------------------------------
// Kernel 6: per-bag stable softmax. One block per bag, fixed-order tree
// reductions (deterministic across graph replays).
// ---------------------------------------------------------------------------
__global__ __launch_bounds__(256)
void bag_softmax_kernel(float* __restrict__ out)
{
    __shared__ float red[256];
    const int b   = blockIdx.x;
    const int tid = threadIdx.x;
    const long long s = g_off[b];
    const long long e = g_off[b + 1];

    float m = NEG_INF_F;
    for (long long i = s + tid; i < e; i += 256) m = fmaxf(m, g_scores[i]);
    red[tid] = m;
    __syncthreads();
    #pragma unroll
    for (int o = 128; o; o >>= 1) {
        if (tid < o) red[tid] = fmaxf(red[tid], red[tid + o]);
        __syncthreads();
    }
    const float M = red[0];
    __syncthreads();

    float z = 0.f;
    for (long long i = s + tid; i < e; i += 256) {
        float ev = expf(g_scores[i] - M);
        out[i] = ev;
        z += ev;
    }
    red[tid] = z;
    __syncthreads();
    #pragma unroll
    for (int o = 128; o; o >>= 1) {
        if (tid < o) red[tid] += red[tid + o];
        __syncthreads();
    }
    const float inv = 1.0f / red[0];
    for (long long i = s + tid; i < e; i += 256) out[i] *= inv;
}

// ---------------------------------------------------------------------------
// Launch: inputs per metadata order:
// 0 features[N,1024] f32, 1 bag_sizes[128] i32, 2 W1[1024,256] f32, 3 b1[256],
// 4 gamma[256], 5 beta[256], 6 W2[256,1], 7 b2[1].  Output: att[N,1] f32.
// ---------------------------------------------------------------------------
extern "C" void kernel_launch(void* const* d_in, const int* in_sizes, int n_in,
                              void* d_out, int out_size)
{
    const float* features  = (const float*)d_in[0];
    const int*   bag_sizes = (const int*)d_in[1];     // int32 per harness convention
    const float* W1        = (const float*)d_in[2];
    const float* b1        = (const float*)d_in[3];
    const float* gamma     = (const float*)d_in[4];
    const float* beta      = (const float*)d_in[5];
    const float* W2        = (const float*)d_in[6];
    const float* b2        = (const float*)d_in[7];
    float*       out       = (float*)d_out;

    const int n      = out_size;        // 262144 rows
    const int n_bags = in_sizes[1];     // 128

    dim3 gemm_grid(DHID / 128, (n + 127) / 128);
    sgemm_kernel<<<gemm_grid, 256>>>(features, W1, b1, n);
    stats_partial_kernel<<<STAT_BLOCKS, 256>>>(n);
    stats_final_kernel<<<1, 256>>>(gamma, beta, n);
    scores_kernel<<<(n + 7) / 8, 256>>>(W2, b2, n);
    offsets_kernel<<<1, 1>>>(bag_sizes, n_bags);
    bag_softmax_kernel<<<n_bags, 256>>>(out);
}

// round 6
// speedup vs baseline: 1.7160x; 1.7160x over previous
#include <cuda_runtime.h>
#include <cuda_bf16.h>
#include <cstdint>

// Problem dims (fixed): N=262144 rows, d_in=1024, d_hid=256, 128 bags.
#define NROWS_MAX 262144
#define DIN 1024
#define DHID 256
#define STAT_BLOCKS 512
#define NEG_INF_F (__int_as_float(0xff800000))

// Scratch (__device__ globals; no allocations allowed)
__device__ float          g_h[(size_t)NROWS_MAX * DHID];   // 256 MB activations
__device__ float          g_scores[NROWS_MAX];
__device__ float          g_psum[STAT_BLOCKS * DHID];
__device__ float          g_psumsq[STAT_BLOCKS * DHID];
__device__ float          g_bn_a[DHID];
__device__ float          g_bn_c[DHID];
__device__ long long      g_off[1025];
__device__ unsigned short g_Bhi[(size_t)DHID * DIN];       // W1^T hi bf16 [256][1024] (K-major)
__device__ unsigned short g_Blo[(size_t)DHID * DIN];       // W1^T lo bf16

// ---------------- helpers ----------------
__device__ __forceinline__ uint32_t smem_u32(const void* p) {
    uint32_t a;
    asm("{ .reg .u64 t; cvta.to.shared.u64 t, %1; cvt.u32.u64 %0, t; }" : "=r"(a) : "l"(p));
    return a;
}
// pack two floats' TOP 16 bits -> bf16x2 (truncation; memory order a then b)
__device__ __forceinline__ uint32_t prm_hi(float a, float b) {
    return __byte_perm(__float_as_uint(a), __float_as_uint(b), 0x7632);
}
// round-to-nearest bf16x2 pack, memory order: first, second
__device__ __forceinline__ uint32_t pack2(float first, float second) {
    uint32_t r;
    asm("cvt.rn.bf16x2.f32 %0, %1, %2;" : "=r"(r) : "f"(second), "f"(first));
    return r;
}
__device__ __forceinline__ float trunc_hi(float x) {
    return __uint_as_float(__float_as_uint(x) & 0xFFFF0000u);
}
__device__ __forceinline__ void ldm4(uint32_t* r, uint32_t addr) {
    asm volatile("ldmatrix.sync.aligned.m8n8.x4.shared.b16 {%0,%1,%2,%3}, [%4];"
                 : "=r"(r[0]), "=r"(r[1]), "=r"(r[2]), "=r"(r[3]) : "r"(addr));
}
__device__ __forceinline__ void mma16816(float* c, const uint32_t* a, uint32_t b0, uint32_t b1) {
    asm volatile(
        "mma.sync.aligned.m16n8k16.row.col.f32.bf16.bf16.f32 "
        "{%0,%1,%2,%3}, {%4,%5,%6,%7}, {%8,%9}, {%0,%1,%2,%3};"
        : "+f"(c[0]), "+f"(c[1]), "+f"(c[2]), "+f"(c[3])
        : "r"(a[0]), "r"(a[1]), "r"(a[2]), "r"(a[3]), "r"(b0), "r"(b1));
}

// ---------------------------------------------------------------------------
// Kernel 0: W1 [1024][256] fp32 -> g_Bhi/g_Blo [256][1024] split-bf16 (K-major)
// ---------------------------------------------------------------------------
__global__ __launch_bounds__(256)
void convert_w1_kernel(const float* __restrict__ W1)
{
    const int n = blockIdx.x;
    const int t = threadIdx.x;
    #pragma unroll
    for (int i = 0; i < DIN / 256; ++i) {
        int k = t + 256 * i;
        float x = W1[(size_t)k * DHID + n];
        uint32_t xb = __float_as_uint(x);
        float hi = __uint_as_float(xb & 0xFFFF0000u);
        float lo = x - hi;
        g_Bhi[(size_t)n * DIN + k] = (unsigned short)(xb >> 16);
        __nv_bfloat16 lb = __float2bfloat16_rn(lo);
        g_Blo[(size_t)n * DIN + k] = *(unsigned short*)&lb;
    }
}

// ---------------------------------------------------------------------------
// Kernel 1: mma.sync bf16 split GEMM  h = features @ W1 + b1
// CTA tile 128m x 128n (grid.x=2 covers n=256). 8 warps: 4(m) x 2(n),
// warp tile 32x64. K chunks of 32, double-buffered smem, reg prefetch.
// Smem row layout (per m/n row): 128B = hi[32 bf16] | lo[32 bf16],
// 16B units XOR-swizzled by (row&7) -> conflict-free ldmatrix.
// ---------------------------------------------------------------------------
__global__ __launch_bounds__(256, 1)
void gemm_mma_kernel(const float* __restrict__ A, const float* __restrict__ b1, int nrows)
{
    extern __shared__ __align__(16) char sm[];
    __shared__ float sbias[128];

    const int tid  = threadIdx.x;
    const int wid  = tid >> 5;
    const int lane = tid & 31;
    const int n0   = blockIdx.x * 128;
    const int row0 = blockIdx.y * 128;

    const uint32_t smbase = smem_u32(sm);
    // per-buffer: A 16KB at +0, B 16KB at +16384; buffers at 0 / 32768
    const int BUF = 32768;

    if (tid < 128) sbias[tid] = b1[n0 + tid];

    // ---- staging maps ----
    const int arow = tid >> 1;                 // 0..127
    const int akq  = (tid & 1) * 16;           // k sub-offset
    const float* abase = A + (size_t)(row0 + arow) * DIN + akq;
    const int au0 = (tid & 1) * 2;             // hi unit base 0 or 2
    char* a_st[4];
    {
        char* arow_p = sm + arow * 128;
        a_st[0] = arow_p + (((au0 + 0) ^ (arow & 7)) << 4);
        a_st[1] = arow_p + (((au0 + 1) ^ (arow & 7)) << 4);
        a_st[2] = arow_p + (((au0 + 4) ^ (arow & 7)) << 4);
        a_st[3] = arow_p + (((au0 + 5) ^ (arow & 7)) << 4);
    }
    const int bn1 = tid >> 2;                  // 0..63
    const int bn2 = bn1 + 64;                  // 64..127
    const int bu  = tid & 3;
    const unsigned short* bh1p = g_Bhi + (size_t)(n0 + bn1) * DIN + bu * 8;
    const unsigned short* bh2p = g_Bhi + (size_t)(n0 + bn2) * DIN + bu * 8;
    const unsigned short* bl1p = g_Blo + (size_t)(n0 + bn1) * DIN + bu * 8;
    const unsigned short* bl2p = g_Blo + (size_t)(n0 + bn2) * DIN + bu * 8;
    char* b_st[4];
    {
        char* b1p = sm + 16384 + bn1 * 128;
        char* b2p = sm + 16384 + bn2 * 128;
        b_st[0] = b1p + (((bu    ) ^ (bn1 & 7)) << 4);
        b_st[1] = b2p + (((bu    ) ^ (bn2 & 7)) << 4);
        b_st[2] = b1p + (((bu + 4) ^ (bn1 & 7)) << 4);
        b_st[3] = b2p + (((bu + 4) ^ (bn2 & 7)) << 4);
    }

    // ---- stage chunk 0 into buffer 0 ----
    {
        const float4* ap = (const float4*)abase;
        float4 f0 = ap[0], f1 = ap[1], f2 = ap[2], f3 = ap[3];
        uint4 hq0 = make_uint4(prm_hi(f0.x, f0.y), prm_hi(f0.z, f0.w),
                               prm_hi(f1.x, f1.y), prm_hi(f1.z, f1.w));
        uint4 hq1 = make_uint4(prm_hi(f2.x, f2.y), prm_hi(f2.z, f2.w),
                               prm_hi(f3.x, f3.y), prm_hi(f3.z, f3.w));
        uint4 lq0 = make_uint4(pack2(f0.x - trunc_hi(f0.x), f0.y - trunc_hi(f0.y)),
                               pack2(f0.z - trunc_hi(f0.z), f0.w - trunc_hi(f0.w)),
                               pack2(f1.x - trunc_hi(f1.x), f1.y - trunc_hi(f1.y)),
                               pack2(f1.z - trunc_hi(f1.z), f1.w - trunc_hi(f1.w)));
        uint4 lq1 = make_uint4(pack2(f2.x - trunc_hi(f2.x), f2.y - trunc_hi(f2.y)),
                               pack2(f2.z - trunc_hi(f2.z), f2.w - trunc_hi(f2.w)),
                               pack2(f3.x - trunc_hi(f3.x), f3.y - trunc_hi(f3.y)),
                               pack2(f3.z - trunc_hi(f3.z), f3.w - trunc_hi(f3.w)));
        *(uint4*)(a_st[0]) = hq0;  *(uint4*)(a_st[1]) = hq1;
        *(uint4*)(a_st[2]) = lq0;  *(uint4*)(a_st[3]) = lq1;
        *(uint4*)(b_st[0]) = *(const uint4*)(bh1p);
        *(uint4*)(b_st[1]) = *(const uint4*)(bh2p);
        *(uint4*)(b_st[2]) = *(const uint4*)(bl1p);
        *(uint4*)(b_st[3]) = *(const uint4*)(bl2p);
    }
    __syncthreads();

    // ---- warp compute mapping ----
    const int m0w = (wid & 3) * 32;
    const int n0w = (wid >> 2) * 64;
    const int lr  = lane & 15;
    const int lsel = (lane >> 4) & 1;

    float acc[2][8][4];
    #pragma unroll
    for (int mt = 0; mt < 2; ++mt)
        #pragma unroll
        for (int nt = 0; nt < 8; ++nt)
            #pragma unroll
            for (int q = 0; q < 4; ++q) acc[mt][nt][q] = 0.f;

    const int NKC = DIN / 32;  // 32 chunks
    for (int kc = 0; kc < NKC; ++kc) {
        const uint32_t cur = (uint32_t)(kc & 1) * BUF;
        const bool pf = (kc + 1) < NKC;

        // prefetch next chunk into registers (LDG issued before MMA block)
        float4 f0, f1, f2, f3;
        uint4 q0, q1, q2, q3;
        if (pf) {
            const float4* ap = (const float4*)(abase + (kc + 1) * 32);
            f0 = ap[0]; f1 = ap[1]; f2 = ap[2]; f3 = ap[3];
            q0 = *(const uint4*)(bh1p + (kc + 1) * 32);
            q1 = *(const uint4*)(bh2p + (kc + 1) * 32);
            q2 = *(const uint4*)(bl1p + (kc + 1) * 32);
            q3 = *(const uint4*)(bl2p + (kc + 1) * 32);
        }

        // ---- MMAs on current buffer ----
        #pragma unroll
        for (int ks = 0; ks < 2; ++ks) {
            uint32_t ah[2][4], al[2][4];
            #pragma unroll
            for (int mt = 0; mt < 2; ++mt) {
                int r = m0w + mt * 16 + lr;
                uint32_t ubh = (uint32_t)(2 * ks + lsel);
                uint32_t base = smbase + cur + r * 128;
                ldm4(ah[mt], base + (((ubh    ) ^ (r & 7)) << 4));
                ldm4(al[mt], base + (((ubh + 4) ^ (r & 7)) << 4));
            }
            #pragma unroll
            for (int p = 0; p < 4; ++p) {
                uint32_t bh[4], bl[4];
                int rn = n0w + p * 16 + lr;
                uint32_t ubh = (uint32_t)(2 * ks + lsel);
                uint32_t base = smbase + cur + 16384 + rn * 128;
                ldm4(bh, base + (((ubh    ) ^ (rn & 7)) << 4));
                ldm4(bl, base + (((ubh + 4) ^ (rn & 7)) << 4));
                #pragma unroll
                for (int mt = 0; mt < 2; ++mt) {
                    mma16816(acc[mt][2 * p],     ah[mt], bh[0], bh[2]);
                    mma16816(acc[mt][2 * p],     ah[mt], bl[0], bl[2]);
                    mma16816(acc[mt][2 * p],     al[mt], bh[0], bh[2]);
                    mma16816(acc[mt][2 * p + 1], ah[mt], bh[1], bh[3]);
                    mma16816(acc[mt][2 * p + 1], ah[mt], bl[1], bl[3]);
                    mma16816(acc[mt][2 * p + 1], al[mt], bh[1], bh[3]);
                }
            }
        }

        // ---- convert + store next chunk into other buffer ----
        if (pf) {
            const uint32_t nxt = (uint32_t)((kc + 1) & 1) * BUF;
            uint4 hq0 = make_uint4(prm_hi(f0.x, f0.y), prm_hi(f0.z, f0.w),
                                   prm_hi(f1.x, f1.y), prm_hi(f1.z, f1.w));
            uint4 hq1 = make_uint4(prm_hi(f2.x, f2.y), prm_hi(f2.z, f2.w),
                                   prm_hi(f3.x, f3.y), prm_hi(f3.z, f3.w));
            uint4 lq0 = make_uint4(pack2(f0.x - trunc_hi(f0.x), f0.y - trunc_hi(f0.y)),
                                   pack2(f0.z - trunc_hi(f0.z), f0.w - trunc_hi(f0.w)),
                                   pack2(f1.x - trunc_hi(f1.x), f1.y - trunc_hi(f1.y)),
                                   pack2(f1.z - trunc_hi(f1.z), f1.w - trunc_hi(f1.w)));
            uint4 lq1 = make_uint4(pack2(f2.x - trunc_hi(f2.x), f2.y - trunc_hi(f2.y)),
                                   pack2(f2.z - trunc_hi(f2.z), f2.w - trunc_hi(f2.w)),
                                   pack2(f3.x - trunc_hi(f3.x), f3.y - trunc_hi(f3.y)),
                                   pack2(f3.z - trunc_hi(f3.z), f3.w - trunc_hi(f3.w)));
            *(uint4*)(a_st[0] + nxt) = hq0;  *(uint4*)(a_st[1] + nxt) = hq1;
            *(uint4*)(a_st[2] + nxt) = lq0;  *(uint4*)(a_st[3] + nxt) = lq1;
            *(uint4*)(b_st[0] + nxt) = q0;   *(uint4*)(b_st[1] + nxt) = q1;
            *(uint4*)(b_st[2] + nxt) = q2;   *(uint4*)(b_st[3] + nxt) = q3;
        }
        __syncthreads();
    }

    // ---- epilogue: bias add, write g_h ----
    const int erow = lane >> 2;
    const int ecol = (lane & 3) * 2;
    #pragma unroll
    for (int mt = 0; mt < 2; ++mt) {
        #pragma unroll
        for (int nt = 0; nt < 8; ++nt) {
            int lc = n0w + nt * 8 + ecol;
            int gc = n0 + lc;
            float bx = sbias[lc], by = sbias[lc + 1];
            int gr0 = row0 + m0w + mt * 16 + erow;
            float2 v0 = make_float2(acc[mt][nt][0] + bx, acc[mt][nt][1] + by);
            float2 v1 = make_float2(acc[mt][nt][2] + bx, acc[mt][nt][3] + by);
            *(float2*)&g_h[(size_t)gr0 * DHID + gc]       = v0;
            *(float2*)&g_h[(size_t)(gr0 + 8) * DHID + gc] = v1;
        }
    }
}

// ---------------------------------------------------------------------------
// Kernel 2: per-column partial sums / sumsq of g_h
// ---------------------------------------------------------------------------
__global__ __launch_bounds__(256)
void stats_partial_kernel(int nrows)
{
    const int c = threadIdx.x;
    const int b = blockIdx.x;
    const int rows_per = (nrows + gridDim.x - 1) / gridDim.x;
    const int r0 = b * rows_per;
    int r1 = r0 + rows_per;
    if (r1 > nrows) r1 = nrows;
    float s = 0.f, q = 0.f;
    for (int r = r0; r < r1; ++r) {
        float v = g_h[(size_t)r * DHID + c];
        s += v;
        q = fmaf(v, v, q);
    }
    g_psum[b * DHID + c]   = s;
    g_psumsq[b * DHID + c] = q;
}

// Kernel 3: finalize BN coefficients.
__global__ __launch_bounds__(256)
void stats_final_kernel(const float* __restrict__ gamma,
                        const float* __restrict__ beta, int nrows)
{
    const int c = threadIdx.x;
    float s = 0.f, q = 0.f;
    for (int b = 0; b < STAT_BLOCKS; ++b) {
        s += g_psum[b * DHID + c];
        q += g_psumsq[b * DHID + c];
    }
    float inv_n = 1.0f / (float)nrows;
    float mean  = s * inv_n;
    float var   = fmaf(-mean, mean, q * inv_n);
    float rstd  = rsqrtf(var + 1e-5f);
    float a     = gamma[c] * rstd;
    g_bn_a[c] = a;
    g_bn_c[c] = fmaf(-mean, a, beta[c]);
}

// Kernel 4: scores (warp per row)
__global__ __launch_bounds__(256)
void scores_kernel(const float* __restrict__ W2, const float* __restrict__ b2,
                   int nrows)
{
    __shared__ float sa[DHID], sc[DHID], sw[DHID];
    const int tid = threadIdx.x;
    sa[tid] = g_bn_a[tid];
    sc[tid] = g_bn_c[tid];
    sw[tid] = W2[tid];
    __syncthreads();

    const int warp = tid >> 5;
    const int lane = tid & 31;
    const int row  = blockIdx.x * 8 + warp;
    if (row >= nrows) return;

    const float* hr = g_h + (size_t)row * DHID;
    float acc = 0.f;
    #pragma unroll
    for (int part = 0; part < 2; ++part) {
        int c0 = part * 128 + lane * 4;
        float4 v = *(const float4*)(hr + c0);
        acc += fmaxf(fmaf(sa[c0 + 0], v.x, sc[c0 + 0]), 0.f) * sw[c0 + 0];
        acc += fmaxf(fmaf(sa[c0 + 1], v.y, sc[c0 + 1]), 0.f) * sw[c0 + 1];
        acc += fmaxf(fmaf(sa[c0 + 2], v.z, sc[c0 + 2]), 0.f) * sw[c0 + 2];
        acc += fmaxf(fmaf(sa[c0 + 3], v.w, sc[c0 + 3]), 0.f) * sw[c0 + 3];
    }
    #pragma unroll
    for (int o = 16; o; o >>= 1) acc += __shfl_xor_sync(0xffffffffu, acc, o);
    if (lane == 0) g_scores[row] = acc + b2[0];
}

// Kernel 5: bag offsets (bag_sizes is int32 per harness convention)
__global__ void offsets_kernel(const int* __restrict__ bag_sizes, int n_bags)
{
    if (threadIdx.x == 0 && blockIdx.x == 0) {
        long long a = 0;
        g_off[0] = 0;
        for (int b = 0; b < n_bags; ++b) { a += (long long)bag_sizes[b]; g_off[b + 1] = a; }
    }
}

// Kernel 6: per-bag stable softmax (deterministic tree reductions)
__global__ __launch_bounds__(256)
void bag_softmax_kernel(float* __restrict__ out)
{
    __shared__ float red[256];
    const int b   = blockIdx.x;
    const int tid = threadIdx.x;
    const long long s = g_off[b];
    const long long e = g_off[b + 1];

    float m = NEG_INF_F;
    for (long long i = s + tid; i < e; i += 256) m = fmaxf(m, g_scores[i]);
    red[tid] = m;
    __syncthreads();
    #pragma unroll
    for (int o = 128; o; o >>= 1) {
        if (tid < o) red[tid] = fmaxf(red[tid], red[tid + o]);
        __syncthreads();
    }
    const float M = red[0];
    __syncthreads();

    float z = 0.f;
    for (long long i = s + tid; i < e; i += 256) {
        float ev = expf(g_scores[i] - M);
        out[i] = ev;
        z += ev;
    }
    red[tid] = z;
    __syncthreads();
    #pragma unroll
    for (int o = 128; o; o >>= 1) {
        if (tid < o) red[tid] += red[tid + o];
        __syncthreads();
    }
    const float inv = 1.0f / red[0];
    for (long long i = s + tid; i < e; i += 256) out[i] *= inv;
}

// ---------------------------------------------------------------------------
extern "C" void kernel_launch(void* const* d_in, const int* in_sizes, int n_in,
                              void* d_out, int out_size)
{
    const float* features  = (const float*)d_in[0];
    const int*   bag_sizes = (const int*)d_in[1];
    const float* W1        = (const float*)d_in[2];
    const float* b1        = (const float*)d_in[3];
    const float* gamma     = (const float*)d_in[4];
    const float* beta      = (const float*)d_in[5];
    const float* W2        = (const float*)d_in[6];
    const float* b2        = (const float*)d_in[7];
    float*       out       = (float*)d_out;

    const int n      = out_size;        // 262144
    const int n_bags = in_sizes[1];     // 128

    const int GEMM_SMEM = 65536;
    cudaFuncSetAttribute(gemm_mma_kernel,
                         cudaFuncAttributeMaxDynamicSharedMemorySize, GEMM_SMEM);

    convert_w1_kernel<<<DHID, 256>>>(W1);
    dim3 ggrid(2, n / 128);
    gemm_mma_kernel<<<ggrid, 256, GEMM_SMEM>>>(features, b1, n);
    stats_partial_kernel<<<STAT_BLOCKS, 256>>>(n);
    stats_final_kernel<<<1, 256>>>(gamma, beta, n);
    scores_kernel<<<(n + 7) / 8, 256>>>(W2, b2, n);
    offsets_kernel<<<1, 1>>>(bag_sizes, n_bags);
    bag_softmax_kernel<<<n_bags, 256>>>(out);
}

// round 7
// speedup vs baseline: 2.5108x; 1.4631x over previous
#include <cuda_runtime.h>
#include <cuda_bf16.h>
#include <cstdint>

// Problem dims (fixed): N=262144 rows, d_in=1024, d_hid=256, 128 bags.
#define NROWS_MAX 262144
#define DIN 1024
#define DHID 256
#define NEG_INF_F (__int_as_float(0xff800000))

// Scratch (__device__ globals; no allocations allowed)
__device__ float          g_h[(size_t)NROWS_MAX * DHID];   // 256 MB activations
__device__ float          g_scores[NROWS_MAX];
__device__ float          g_psum[4096 * 128];              // per-GEMM-CTA col sums
__device__ float          g_psumsq[4096 * 128];
__device__ float          g_bn_a[DHID];
__device__ float          g_bn_c[DHID];
__device__ long long      g_off[1025];
__device__ unsigned short g_Bhi[(size_t)DHID * DIN];       // W1^T hi bf16 [256][1024] (K-major)
__device__ unsigned short g_Blo[(size_t)DHID * DIN];       // W1^T lo bf16

// ---------------- helpers ----------------
__device__ __forceinline__ uint32_t smem_u32(const void* p) {
    uint32_t a;
    asm("{ .reg .u64 t; cvta.to.shared.u64 t, %1; cvt.u32.u64 %0, t; }" : "=r"(a) : "l"(p));
    return a;
}
__device__ __forceinline__ uint32_t prm_hi(float a, float b) {
    return __byte_perm(__float_as_uint(a), __float_as_uint(b), 0x7632);
}
__device__ __forceinline__ uint32_t pack2(float first, float second) {
    uint32_t r;
    asm("cvt.rn.bf16x2.f32 %0, %1, %2;" : "=r"(r) : "f"(second), "f"(first));
    return r;
}
__device__ __forceinline__ float trunc_hi(float x) {
    return __uint_as_float(__float_as_uint(x) & 0xFFFF0000u);
}
__device__ __forceinline__ void ldm4(uint32_t* r, uint32_t addr) {
    asm volatile("ldmatrix.sync.aligned.m8n8.x4.shared.b16 {%0,%1,%2,%3}, [%4];"
                 : "=r"(r[0]), "=r"(r[1]), "=r"(r[2]), "=r"(r[3]) : "r"(addr));
}
__device__ __forceinline__ void mma16816(float* c, const uint32_t* a, uint32_t b0, uint32_t b1) {
    asm volatile(
        "mma.sync.aligned.m16n8k16.row.col.f32.bf16.bf16.f32 "
        "{%0,%1,%2,%3}, {%4,%5,%6,%7}, {%8,%9}, {%0,%1,%2,%3};"
        : "+f"(c[0]), "+f"(c[1]), "+f"(c[2]), "+f"(c[3])
        : "r"(a[0]), "r"(a[1]), "r"(a[2]), "r"(a[3]), "r"(b0), "r"(b1));
}
#define CP_ASYNC16(dst, src) \
    asm volatile("cp.async.ca.shared.global [%0], [%1], 16;" :: "r"(dst), "l"(src) : "memory")
#define CP_COMMIT()  asm volatile("cp.async.commit_group;" ::: "memory")
#define CP_WAIT0()   asm volatile("cp.async.wait_group 0;" ::: "memory")

// ---------------------------------------------------------------------------
// Kernel 0: W1 [1024][256] fp32 -> g_Bhi/g_Blo [256][1024] split-bf16 (K-major)
// ---------------------------------------------------------------------------
__global__ __launch_bounds__(256)
void convert_w1_kernel(const float* __restrict__ W1)
{
    const int n = blockIdx.x;
    const int t = threadIdx.x;
    #pragma unroll
    for (int i = 0; i < DIN / 256; ++i) {
        int k = t + 256 * i;
        float x = W1[(size_t)k * DHID + n];
        uint32_t xb = __float_as_uint(x);
        float hi = __uint_as_float(xb & 0xFFFF0000u);
        float lo = x - hi;
        g_Bhi[(size_t)n * DIN + k] = (unsigned short)(xb >> 16);
        __nv_bfloat16 lb = __float2bfloat16_rn(lo);
        g_Blo[(size_t)n * DIN + k] = *(unsigned short*)&lb;
    }
}

// ---------------------------------------------------------------------------
// Kernel 1: mma.sync bf16 split GEMM  h = features @ W1 + b1, fused col stats.
// CTA tile 128m x 128n (grid.x=2 covers n=256). 8 warps: 4(m) x 2(n),
// warp tile 32x64. K chunks of 32, double-buffered smem, cp.async for B.
// MMAs issued as 3 independent 16-MMA sweeps (hh, hl, lh) per k-step.
// ---------------------------------------------------------------------------
__global__ __launch_bounds__(256, 1)
void gemm_mma_kernel(const float* __restrict__ A, const float* __restrict__ b1, int nrows)
{
    extern __shared__ __align__(16) char sm[];
    __shared__ float sbias[128];

    const int tid  = threadIdx.x;
    const int wid  = tid >> 5;
    const int lane = tid & 31;
    const int n0   = blockIdx.x * 128;
    const int row0 = blockIdx.y * 128;

    const uint32_t smbase = smem_u32(sm);
    const int BUF = 32768;   // per-buffer: A 16KB @ +0, B 16KB @ +16384

    if (tid < 128) sbias[tid] = b1[n0 + tid];

    // ---- staging maps ----
    const int arow = tid >> 1;
    const int akq  = (tid & 1) * 16;
    const float* abase = A + (size_t)(row0 + arow) * DIN + akq;
    const int au0 = (tid & 1) * 2;
    uint32_t a_of[4];
    {
        uint32_t arow_o = (uint32_t)arow * 128;
        a_of[0] = arow_o + (((au0 + 0) ^ (arow & 7)) << 4);
        a_of[1] = arow_o + (((au0 + 1) ^ (arow & 7)) << 4);
        a_of[2] = arow_o + (((au0 + 4) ^ (arow & 7)) << 4);
        a_of[3] = arow_o + (((au0 + 5) ^ (arow & 7)) << 4);
    }
    const int bn1 = tid >> 2;
    const int bn2 = bn1 + 64;
    const int bu  = tid & 3;
    const unsigned short* bh1p = g_Bhi + (size_t)(n0 + bn1) * DIN + bu * 8;
    const unsigned short* bh2p = g_Bhi + (size_t)(n0 + bn2) * DIN + bu * 8;
    const unsigned short* bl1p = g_Blo + (size_t)(n0 + bn1) * DIN + bu * 8;
    const unsigned short* bl2p = g_Blo + (size_t)(n0 + bn2) * DIN + bu * 8;
    uint32_t b_of[4];
    {
        uint32_t b1o = 16384u + (uint32_t)bn1 * 128;
        uint32_t b2o = 16384u + (uint32_t)bn2 * 128;
        b_of[0] = b1o + (((bu    ) ^ (bn1 & 7)) << 4);
        b_of[1] = b2o + (((bu    ) ^ (bn2 & 7)) << 4);
        b_of[2] = b1o + (((bu + 4) ^ (bn1 & 7)) << 4);
        b_of[3] = b2o + (((bu + 4) ^ (bn2 & 7)) << 4);
    }

    // ---- stage chunk 0 ----
    {
        CP_ASYNC16(smbase + b_of[0], bh1p);
        CP_ASYNC16(smbase + b_of[1], bh2p);
        CP_ASYNC16(smbase + b_of[2], bl1p);
        CP_ASYNC16(smbase + b_of[3], bl2p);
        CP_COMMIT();
        const float4* ap = (const float4*)abase;
        float4 f0 = ap[0], f1 = ap[1], f2 = ap[2], f3 = ap[3];
        *(uint4*)(sm + a_of[0]) = make_uint4(prm_hi(f0.x, f0.y), prm_hi(f0.z, f0.w),
                                             prm_hi(f1.x, f1.y), prm_hi(f1.z, f1.w));
        *(uint4*)(sm + a_of[1]) = make_uint4(prm_hi(f2.x, f2.y), prm_hi(f2.z, f2.w),
                                             prm_hi(f3.x, f3.y), prm_hi(f3.z, f3.w));
        *(uint4*)(sm + a_of[2]) = make_uint4(pack2(f0.x - trunc_hi(f0.x), f0.y - trunc_hi(f0.y)),
                                             pack2(f0.z - trunc_hi(f0.z), f0.w - trunc_hi(f0.w)),
                                             pack2(f1.x - trunc_hi(f1.x), f1.y - trunc_hi(f1.y)),
                                             pack2(f1.z - trunc_hi(f1.z), f1.w - trunc_hi(f1.w)));
        *(uint4*)(sm + a_of[3]) = make_uint4(pack2(f2.x - trunc_hi(f2.x), f2.y - trunc_hi(f2.y)),
                                             pack2(f2.z - trunc_hi(f2.z), f2.w - trunc_hi(f2.w)),
                                             pack2(f3.x - trunc_hi(f3.x), f3.y - trunc_hi(f3.y)),
                                             pack2(f3.z - trunc_hi(f3.z), f3.w - trunc_hi(f3.w)));
        CP_WAIT0();
    }
    __syncthreads();

    // ---- warp compute mapping ----
    const int m0w  = (wid & 3) * 32;
    const int n0w  = (wid >> 2) * 64;
    const int lr   = lane & 15;
    const int lsel = (lane >> 4) & 1;

    float acc[2][8][4];
    #pragma unroll
    for (int mt = 0; mt < 2; ++mt)
        #pragma unroll
        for (int nt = 0; nt < 8; ++nt)
            #pragma unroll
            for (int q = 0; q < 4; ++q) acc[mt][nt][q] = 0.f;

    const int NKC = DIN / 32;
    for (int kc = 0; kc < NKC; ++kc) {
        const uint32_t cur = (uint32_t)(kc & 1) * BUF;
        const bool pf = (kc + 1) < NKC;
        const uint32_t nxt = (uint32_t)((kc + 1) & 1) * BUF;

        float4 f0, f1, f2, f3;
        if (pf) {
            CP_ASYNC16(smbase + nxt + b_of[0], bh1p + (kc + 1) * 32);
            CP_ASYNC16(smbase + nxt + b_of[1], bh2p + (kc + 1) * 32);
            CP_ASYNC16(smbase + nxt + b_of[2], bl1p + (kc + 1) * 32);
            CP_ASYNC16(smbase + nxt + b_of[3], bl2p + (kc + 1) * 32);
            CP_COMMIT();
            const float4* ap = (const float4*)(abase + (kc + 1) * 32);
            f0 = ap[0]; f1 = ap[1]; f2 = ap[2]; f3 = ap[3];
        }

        #pragma unroll
        for (int ks = 0; ks < 2; ++ks) {
            // hoist all fragments
            uint32_t ah[2][4], al[2][4], bh[4][4], bl[4][4];
            const uint32_t ubh = (uint32_t)(2 * ks + lsel);
            #pragma unroll
            for (int mt = 0; mt < 2; ++mt) {
                int r = m0w + mt * 16 + lr;
                uint32_t base = smbase + cur + r * 128;
                ldm4(ah[mt], base + (((ubh    ) ^ (r & 7)) << 4));
                ldm4(al[mt], base + (((ubh + 4) ^ (r & 7)) << 4));
            }
            #pragma unroll
            for (int p = 0; p < 4; ++p) {
                int rn = n0w + p * 16 + lr;
                uint32_t base = smbase + cur + 16384 + rn * 128;
                ldm4(bh[p], base + (((ubh    ) ^ (rn & 7)) << 4));
                ldm4(bl[p], base + (((ubh + 4) ^ (rn & 7)) << 4));
            }
            // three independent sweeps of 16 MMAs each (no acc reuse within sweep)
            #pragma unroll
            for (int p = 0; p < 4; ++p)
                #pragma unroll
                for (int mt = 0; mt < 2; ++mt) {
                    mma16816(acc[mt][2 * p],     ah[mt], bh[p][0], bh[p][2]);
                    mma16816(acc[mt][2 * p + 1], ah[mt], bh[p][1], bh[p][3]);
                }
            #pragma unroll
            for (int p = 0; p < 4; ++p)
                #pragma unroll
                for (int mt = 0; mt < 2; ++mt) {
                    mma16816(acc[mt][2 * p],     ah[mt], bl[p][0], bl[p][2]);
                    mma16816(acc[mt][2 * p + 1], ah[mt], bl[p][1], bl[p][3]);
                }
            #pragma unroll
            for (int p = 0; p < 4; ++p)
                #pragma unroll
                for (int mt = 0; mt < 2; ++mt) {
                    mma16816(acc[mt][2 * p],     al[mt], bh[p][0], bh[p][2]);
                    mma16816(acc[mt][2 * p + 1], al[mt], bh[p][1], bh[p][3]);
                }
        }

        if (pf) {
            *(uint4*)(sm + nxt + a_of[0]) = make_uint4(prm_hi(f0.x, f0.y), prm_hi(f0.z, f0.w),
                                                       prm_hi(f1.x, f1.y), prm_hi(f1.z, f1.w));
            *(uint4*)(sm + nxt + a_of[1]) = make_uint4(prm_hi(f2.x, f2.y), prm_hi(f2.z, f2.w),
                                                       prm_hi(f3.x, f3.y), prm_hi(f3.z, f3.w));
            *(uint4*)(sm + nxt + a_of[2]) = make_uint4(
                pack2(f0.x - trunc_hi(f0.x), f0.y - trunc_hi(f0.y)),
                pack2(f0.z - trunc_hi(f0.z), f0.w - trunc_hi(f0.w)),
                pack2(f1.x - trunc_hi(f1.x), f1.y - trunc_hi(f1.y)),
                pack2(f1.z - trunc_hi(f1.z), f1.w - trunc_hi(f1.w)));
            *(uint4*)(sm + nxt + a_of[3]) = make_uint4(
                pack2(f2.x - trunc_hi(f2.x), f2.y - trunc_hi(f2.y)),
                pack2(f2.z - trunc_hi(f2.z), f2.w - trunc_hi(f2.w)),
                pack2(f3.x - trunc_hi(f3.x), f3.y - trunc_hi(f3.y)),
                pack2(f3.z - trunc_hi(f3.z), f3.w - trunc_hi(f3.w)));
            CP_WAIT0();
        }
        __syncthreads();
    }

    // ---- epilogue: bias add, write g_h, fused column sum/sumsq ----
    const int erow = lane >> 2;
    const int ecol = (lane & 3) * 2;
    float* ss = (float*)sm;                 // [8][8][4][2] = 512 floats
    float* qq = (float*)(sm + 2048);
    #pragma unroll
    for (int nt = 0; nt < 8; ++nt) {
        int lc = n0w + nt * 8 + ecol;
        int gc = n0 + lc;
        float bx = sbias[lc], by = sbias[lc + 1];
        float sx = 0.f, sy = 0.f, qx = 0.f, qy = 0.f;
        #pragma unroll
        for (int mt = 0; mt < 2; ++mt) {
            int gr0 = row0 + m0w + mt * 16 + erow;
            float2 v0 = make_float2(acc[mt][nt][0] + bx, acc[mt][nt][1] + by);
            float2 v1 = make_float2(acc[mt][nt][2] + bx, acc[mt][nt][3] + by);
            *(float2*)&g_h[(size_t)gr0 * DHID + gc]       = v0;
            *(float2*)&g_h[(size_t)(gr0 + 8) * DHID + gc] = v1;
            sx += v0.x + v1.x;  sy += v0.y + v1.y;
            qx = fmaf(v0.x, v0.x, fmaf(v1.x, v1.x, qx));
            qy = fmaf(v0.y, v0.y, fmaf(v1.y, v1.y, qy));
        }
        #pragma unroll
        for (int o = 4; o < 32; o <<= 1) {
            sx += __shfl_xor_sync(0xffffffffu, sx, o);
            sy += __shfl_xor_sync(0xffffffffu, sy, o);
            qx += __shfl_xor_sync(0xffffffffu, qx, o);
            qy += __shfl_xor_sync(0xffffffffu, qy, o);
        }
        if (lane < 4) {
            int idx = ((wid * 8 + nt) * 4 + lane) * 2;
            ss[idx] = sx;  ss[idx + 1] = sy;
            qq[idx] = qx;  qq[idx + 1] = qy;
        }
    }
    __syncthreads();
    if (tid < 128) {
        const int lc = tid;
        const int hi = (lc >= 64);
        const int within = lc - hi * 64;
        const int nt  = within >> 3;
        const int grp = (within & 7) >> 1;
        const int xy  = within & 1;
        float s = 0.f, q = 0.f;
        #pragma unroll
        for (int w = 0; w < 4; ++w) {
            int wd = hi * 4 + w;
            int idx = ((wd * 8 + nt) * 4 + grp) * 2 + xy;
            s += ss[idx];
            q += qq[idx];
        }
        int cta = blockIdx.y * 2 + blockIdx.x;
        g_psum[cta * 128 + lc]   = s;
        g_psumsq[cta * 128 + lc] = q;
    }
}

// ---------------------------------------------------------------------------
// Kernel 3: finalize BN coefficients. 256 blocks (one per column), tree reduce.
// ---------------------------------------------------------------------------
__global__ __launch_bounds__(256)
void stats_final_kernel(const float* __restrict__ gamma,
                        const float* __restrict__ beta, int nrows)
{
    __shared__ float rs[256], rq[256];
    const int c   = blockIdx.x;
    const int x   = c >> 7;
    const int lc  = c & 127;
    const int tid = threadIdx.x;
    float s = 0.f, q = 0.f;
    for (int y = tid; y < 2048; y += 256) {
        int cta = y * 2 + x;
        s += g_psum[cta * 128 + lc];
        q += g_psumsq[cta * 128 + lc];
    }
    rs[tid] = s; rq[tid] = q;
    __syncthreads();
    #pragma unroll
    for (int o = 128; o; o >>= 1) {
        if (tid < o) { rs[tid] += rs[tid + o]; rq[tid] += rq[tid + o]; }
        __syncthreads();
    }
    if (tid == 0) {
        float inv_n = 1.0f / (float)nrows;
        float mean  = rs[0] * inv_n;
        float var   = fmaf(-mean, mean, rq[0] * inv_n);
        float rstd  = rsqrtf(var + 1e-5f);
        float a     = gamma[c] * rstd;
        g_bn_a[c] = a;
        g_bn_c[c] = fmaf(-mean, a, beta[c]);
    }
}

// Kernel 4: scores (warp per row)
__global__ __launch_bounds__(256)
void scores_kernel(const float* __restrict__ W2, const float* __restrict__ b2,
                   int nrows)
{
    __shared__ float sa[DHID], sc[DHID], sw[DHID];
    const int tid = threadIdx.x;
    sa[tid] = g_bn_a[tid];
    sc[tid] = g_bn_c[tid];
    sw[tid] = W2[tid];
    __syncthreads();

    const int warp = tid >> 5;
    const int lane = tid & 31;
    const int row  = blockIdx.x * 8 + warp;
    if (row >= nrows) return;

    const float* hr = g_h + (size_t)row * DHID;
    float acc = 0.f;
    #pragma unroll
    for (int part = 0; part < 2; ++part) {
        int c0 = part * 128 + lane * 4;
        float4 v = *(const float4*)(hr + c0);
        acc += fmaxf(fmaf(sa[c0 + 0], v.x, sc[c0 + 0]), 0.f) * sw[c0 + 0];
        acc += fmaxf(fmaf(sa[c0 + 1], v.y, sc[c0 + 1]), 0.f) * sw[c0 + 1];
        acc += fmaxf(fmaf(sa[c0 + 2], v.z, sc[c0 + 2]), 0.f) * sw[c0 + 2];
        acc += fmaxf(fmaf(sa[c0 + 3], v.w, sc[c0 + 3]), 0.f) * sw[c0 + 3];
    }
    #pragma unroll
    for (int o = 16; o; o >>= 1) acc += __shfl_xor_sync(0xffffffffu, acc, o);
    if (lane == 0) g_scores[row] = acc + b2[0];
}

// Kernel 5: bag offsets (bag_sizes is int32 per harness convention)
__global__ void offsets_kernel(const int* __restrict__ bag_sizes, int n_bags)
{
    if (threadIdx.x == 0 && blockIdx.x == 0) {
        long long a = 0;
        g_off[0] = 0;
        for (int b = 0; b < n_bags; ++b) { a += (long long)bag_sizes[b]; g_off[b + 1] = a; }
    }
}

// Kernel 6: per-bag stable softmax (deterministic tree reductions)
__global__ __launch_bounds__(256)
void bag_softmax_kernel(float* __restrict__ out)
{
    __shared__ float red[256];
    const int b   = blockIdx.x;
    const int tid = threadIdx.x;
    const long long s = g_off[b];
    const long long e = g_off[b + 1];

    float m = NEG_INF_F;
    for (long long i = s + tid; i < e; i += 256) m = fmaxf(m, g_scores[i]);
    red[tid] = m;
    __syncthreads();
    #pragma unroll
    for (int o = 128; o; o >>= 1) {
        if (tid < o) red[tid] = fmaxf(red[tid], red[tid + o]);
        __syncthreads();
    }
    const float M = red[0];
    __syncthreads();

    float z = 0.f;
    for (long long i = s + tid; i < e; i += 256) {
        float ev = expf(g_scores[i] - M);
        out[i] = ev;
        z += ev;
    }
    red[tid] = z;
    __syncthreads();
    #pragma unroll
    for (int o = 128; o; o >>= 1) {
        if (tid < o) red[tid] += red[tid + o];
        __syncthreads();
    }
    const float inv = 1.0f / red[0];
    for (long long i = s + tid; i < e; i += 256) out[i] *= inv;
}

// ---------------------------------------------------------------------------
extern "C" void kernel_launch(void* const* d_in, const int* in_sizes, int n_in,
                              void* d_out, int out_size)
{
    const float* features  = (const float*)d_in[0];
    const int*   bag_sizes = (const int*)d_in[1];
    const float* W1        = (const float*)d_in[2];
    const float* b1        = (const float*)d_in[3];
    const float* gamma     = (const float*)d_in[4];
    const float* beta      = (const float*)d_in[5];
    const float* W2        = (const float*)d_in[6];
    const float* b2        = (const float*)d_in[7];
    float*       out       = (float*)d_out;

    const int n      = out_size;        // 262144
    const int n_bags = in_sizes[1];     // 128

    const int GEMM_SMEM = 65536;
    cudaFuncSetAttribute(gemm_mma_kernel,
                         cudaFuncAttributeMaxDynamicSharedMemorySize, GEMM_SMEM);

    convert_w1_kernel<<<DHID, 256>>>(W1);
    dim3 ggrid(2, n / 128);
    gemm_mma_kernel<<<ggrid, 256, GEMM_SMEM>>>(features, b1, n);
    stats_final_kernel<<<DHID, 256>>>(gamma, beta, n);
    scores_kernel<<<(n + 7) / 8, 256>>>(W2, b2, n);
    offsets_kernel<<<1, 1>>>(bag_sizes, n_bags);
    bag_softmax_kernel<<<n_bags, 256>>>(out);
}

// round 8
// speedup vs baseline: 2.7805x; 1.1074x over previous
#include <cuda_runtime.h>
#include <cuda_bf16.h>
#include <cstdint>

// Problem dims (fixed): N=262144 rows, d_in=1024, d_hid=256, 128 bags.
#define NROWS_MAX 262144
#define DIN 1024
#define DHID 256
#define NEG_INF_F (__int_as_float(0xff800000))

__device__ float          g_h[(size_t)NROWS_MAX * DHID];
__device__ float          g_scores[NROWS_MAX];
__device__ float          g_psum[4096 * 128];
__device__ float          g_psumsq[4096 * 128];
__device__ float          g_bn_a[DHID];
__device__ float          g_bn_c[DHID];
__device__ long long      g_off[1025];
__device__ unsigned short g_Bhi[(size_t)DHID * DIN];
__device__ unsigned short g_Blo[(size_t)DHID * DIN];

// ---------------- helpers ----------------
__device__ __forceinline__ uint32_t smem_u32(const void* p) {
    uint32_t a;
    asm("{ .reg .u64 t; cvta.to.shared.u64 t, %1; cvt.u32.u64 %0, t; }" : "=r"(a) : "l"(p));
    return a;
}
__device__ __forceinline__ uint32_t prm_hi(float a, float b) {
    return __byte_perm(__float_as_uint(a), __float_as_uint(b), 0x7632);
}
__device__ __forceinline__ uint32_t pack2(float first, float second) {
    uint32_t r;
    asm("cvt.rn.bf16x2.f32 %0, %1, %2;" : "=r"(r) : "f"(second), "f"(first));
    return r;
}
__device__ __forceinline__ float trunc_hi(float x) {
    return __uint_as_float(__float_as_uint(x) & 0xFFFF0000u);
}
__device__ __forceinline__ void ldm4(uint32_t* r, uint32_t addr) {
    asm volatile("ldmatrix.sync.aligned.m8n8.x4.shared.b16 {%0,%1,%2,%3}, [%4];"
                 : "=r"(r[0]), "=r"(r[1]), "=r"(r[2]), "=r"(r[3]) : "r"(addr));
}
__device__ __forceinline__ void mma16816(float* c, const uint32_t* a, uint32_t b0, uint32_t b1) {
    asm volatile(
        "mma.sync.aligned.m16n8k16.row.col.f32.bf16.bf16.f32 "
        "{%0,%1,%2,%3}, {%4,%5,%6,%7}, {%8,%9}, {%0,%1,%2,%3};"
        : "+f"(c[0]), "+f"(c[1]), "+f"(c[2]), "+f"(c[3])
        : "r"(a[0]), "r"(a[1]), "r"(a[2]), "r"(a[3]), "r"(b0), "r"(b1));
}
#define CP_ASYNC16(dst, src) \
    asm volatile("cp.async.ca.shared.global [%0], [%1], 16;" :: "r"(dst), "l"(src) : "memory")
#define CP_COMMIT()  asm volatile("cp.async.commit_group;" ::: "memory")
#define CP_WAIT0()   asm volatile("cp.async.wait_group 0;" ::: "memory")

// ---------------------------------------------------------------------------
// Kernel 0: W1 split to bf16 hi/lo, K-major
// ---------------------------------------------------------------------------
__global__ __launch_bounds__(256)
void convert_w1_kernel(const float* __restrict__ W1)
{
    const int n = blockIdx.x;
    const int t = threadIdx.x;
    #pragma unroll
    for (int i = 0; i < DIN / 256; ++i) {
        int k = t + 256 * i;
        float x = W1[(size_t)k * DHID + n];
        uint32_t xb = __float_as_uint(x);
        float hi = __uint_as_float(xb & 0xFFFF0000u);
        float lo = x - hi;
        g_Bhi[(size_t)n * DIN + k] = (unsigned short)(xb >> 16);
        __nv_bfloat16 lb = __float2bfloat16_rn(lo);
        g_Blo[(size_t)n * DIN + k] = *(unsigned short*)&lb;
    }
}

// ---------------------------------------------------------------------------
// Kernel 1: mma.sync split-bf16 GEMM, occupancy 2, fused column stats
// ---------------------------------------------------------------------------
__global__ __launch_bounds__(256, 2)
void gemm_mma_kernel(const float* __restrict__ A, const float* __restrict__ b1, int nrows)
{
    extern __shared__ __align__(16) char sm[];
    __shared__ float sbias[128];

    const int tid  = threadIdx.x;
    const int wid  = tid >> 5;
    const int lane = tid & 31;
    const int n0   = blockIdx.x * 128;
    const int row0 = blockIdx.y * 128;

    const uint32_t smbase = smem_u32(sm);
    const int BUF = 32768;

    if (tid < 128) sbias[tid] = b1[n0 + tid];

    // staging maps
    const int arow = tid >> 1;
    const int akq  = (tid & 1) * 16;
    const float* abase = A + (size_t)(row0 + arow) * DIN + akq;
    const int au0 = (tid & 1) * 2;
    uint32_t a_of[4];
    {
        uint32_t arow_o = (uint32_t)arow * 128;
        a_of[0] = arow_o + (((au0 + 0) ^ (arow & 7)) << 4);
        a_of[1] = arow_o + (((au0 + 1) ^ (arow & 7)) << 4);
        a_of[2] = arow_o + (((au0 + 4) ^ (arow & 7)) << 4);
        a_of[3] = arow_o + (((au0 + 5) ^ (arow & 7)) << 4);
    }
    const int bn1 = tid >> 2;
    const int bn2 = bn1 + 64;
    const int bu  = tid & 3;
    const unsigned short* bh1p = g_Bhi + (size_t)(n0 + bn1) * DIN + bu * 8;
    const unsigned short* bh2p = g_Bhi + (size_t)(n0 + bn2) * DIN + bu * 8;
    const unsigned short* bl1p = g_Blo + (size_t)(n0 + bn1) * DIN + bu * 8;
    const unsigned short* bl2p = g_Blo + (size_t)(n0 + bn2) * DIN + bu * 8;
    uint32_t b_of[4];
    {
        uint32_t b1o = 16384u + (uint32_t)bn1 * 128;
        uint32_t b2o = 16384u + (uint32_t)bn2 * 128;
        b_of[0] = b1o + (((bu    ) ^ (bn1 & 7)) << 4);
        b_of[1] = b2o + (((bu    ) ^ (bn2 & 7)) << 4);
        b_of[2] = b1o + (((bu + 4) ^ (bn1 & 7)) << 4);
        b_of[3] = b2o + (((bu + 4) ^ (bn2 & 7)) << 4);
    }

    // stage chunk 0
    {
        CP_ASYNC16(smbase + b_of[0], bh1p);
        CP_ASYNC16(smbase + b_of[1], bh2p);
        CP_ASYNC16(smbase + b_of[2], bl1p);
        CP_ASYNC16(smbase + b_of[3], bl2p);
        CP_COMMIT();
        const float4* ap = (const float4*)abase;
        float4 f0 = ap[0], f1 = ap[1], f2 = ap[2], f3 = ap[3];
        *(uint4*)(sm + a_of[0]) = make_uint4(prm_hi(f0.x, f0.y), prm_hi(f0.z, f0.w),
                                             prm_hi(f1.x, f1.y), prm_hi(f1.z, f1.w));
        *(uint4*)(sm + a_of[1]) = make_uint4(prm_hi(f2.x, f2.y), prm_hi(f2.z, f2.w),
                                             prm_hi(f3.x, f3.y), prm_hi(f3.z, f3.w));
        *(uint4*)(sm + a_of[2]) = make_uint4(pack2(f0.x - trunc_hi(f0.x), f0.y - trunc_hi(f0.y)),
                                             pack2(f0.z - trunc_hi(f0.z), f0.w - trunc_hi(f0.w)),
                                             pack2(f1.x - trunc_hi(f1.x), f1.y - trunc_hi(f1.y)),
                                             pack2(f1.z - trunc_hi(f1.z), f1.w - trunc_hi(f1.w)));
        *(uint4*)(sm + a_of[3]) = make_uint4(pack2(f2.x - trunc_hi(f2.x), f2.y - trunc_hi(f2.y)),
                                             pack2(f2.z - trunc_hi(f2.z), f2.w - trunc_hi(f2.w)),
                                             pack2(f3.x - trunc_hi(f3.x), f3.y - trunc_hi(f3.y)),
                                             pack2(f3.z - trunc_hi(f3.z), f3.w - trunc_hi(f3.w)));
        CP_WAIT0();
    }
    __syncthreads();

    const int m0w  = (wid & 3) * 32;
    const int n0w  = (wid >> 2) * 64;
    const int lr   = lane & 15;
    const int lsel = (lane >> 4) & 1;

    float acc[2][8][4];
    #pragma unroll
    for (int mt = 0; mt < 2; ++mt)
        #pragma unroll
        for (int nt = 0; nt < 8; ++nt)
            #pragma unroll
            for (int q = 0; q < 4; ++q) acc[mt][nt][q] = 0.f;

    const int NKC = DIN / 32;
    for (int kc = 0; kc < NKC; ++kc) {
        const uint32_t cur = (uint32_t)(kc & 1) * BUF;
        const bool pf = (kc + 1) < NKC;
        const uint32_t nxt = (uint32_t)((kc + 1) & 1) * BUF;

        float4 f0, f1, f2, f3;
        if (pf) {
            CP_ASYNC16(smbase + nxt + b_of[0], bh1p + (kc + 1) * 32);
            CP_ASYNC16(smbase + nxt + b_of[1], bh2p + (kc + 1) * 32);
            CP_ASYNC16(smbase + nxt + b_of[2], bl1p + (kc + 1) * 32);
            CP_ASYNC16(smbase + nxt + b_of[3], bl2p + (kc + 1) * 32);
            CP_COMMIT();
            const float4* ap = (const float4*)(abase + (kc + 1) * 32);
            f0 = ap[0]; f1 = ap[1]; f2 = ap[2]; f3 = ap[3];
        }

        #pragma unroll
        for (int ks = 0; ks < 2; ++ks) {
            uint32_t ah[2][4], al[2][4];
            const uint32_t ubh = (uint32_t)(2 * ks + lsel);
            #pragma unroll
            for (int mt = 0; mt < 2; ++mt) {
                int r = m0w + mt * 16 + lr;
                uint32_t base = smbase + cur + r * 128;
                ldm4(ah[mt], base + (((ubh    ) ^ (r & 7)) << 4));
                ldm4(al[mt], base + (((ubh + 4) ^ (r & 7)) << 4));
            }
            // process B in pairs of p-tiles to cut register pressure;
            // sweeps of 8 independent MMAs keep acc reuse distance = 8.
            #pragma unroll
            for (int ph = 0; ph < 2; ++ph) {
                uint32_t bh[2][4], bl[2][4];
                #pragma unroll
                for (int q = 0; q < 2; ++q) {
                    int rn = n0w + (2 * ph + q) * 16 + lr;
                    uint32_t base = smbase + cur + 16384 + rn * 128;
                    ldm4(bh[q], base + (((ubh    ) ^ (rn & 7)) << 4));
                    ldm4(bl[q], base + (((ubh + 4) ^ (rn & 7)) << 4));
                }
                #pragma unroll
                for (int q = 0; q < 2; ++q)
                    #pragma unroll
                    for (int mt = 0; mt < 2; ++mt) {
                        int p = 2 * ph + q;
                        mma16816(acc[mt][2 * p],     ah[mt], bh[q][0], bh[q][2]);
                        mma16816(acc[mt][2 * p + 1], ah[mt], bh[q][1], bh[q][3]);
                    }
                #pragma unroll
                for (int q = 0; q < 2; ++q)
                    #pragma unroll
                    for (int mt = 0; mt < 2; ++mt) {
                        int p = 2 * ph + q;
                        mma16816(acc[mt][2 * p],     ah[mt], bl[q][0], bl[q][2]);
                        mma16816(acc[mt][2 * p + 1], ah[mt], bl[q][1], bl[q][3]);
                    }
                #pragma unroll
                for (int q = 0; q < 2; ++q)
                    #pragma unroll
                    for (int mt = 0; mt < 2; ++mt) {
                        int p = 2 * ph + q;
                        mma16816(acc[mt][2 * p],     al[mt], bh[q][0], bh[q][2]);
                        mma16816(acc[mt][2 * p + 1], al[mt], bh[q][1], bh[q][3]);
                    }
            }
        }

        if (pf) {
            *(uint4*)(sm + nxt + a_of[0]) = make_uint4(prm_hi(f0.x, f0.y), prm_hi(f0.z, f0.w),
                                                       prm_hi(f1.x, f1.y), prm_hi(f1.z, f1.w));
            *(uint4*)(sm + nxt + a_of[1]) = make_uint4(prm_hi(f2.x, f2.y), prm_hi(f2.z, f2.w),
                                                       prm_hi(f3.x, f3.y), prm_hi(f3.z, f3.w));
            *(uint4*)(sm + nxt + a_of[2]) = make_uint4(
                pack2(f0.x - trunc_hi(f0.x), f0.y - trunc_hi(f0.y)),
                pack2(f0.z - trunc_hi(f0.z), f0.w - trunc_hi(f0.w)),
                pack2(f1.x - trunc_hi(f1.x), f1.y - trunc_hi(f1.y)),
                pack2(f1.z - trunc_hi(f1.z), f1.w - trunc_hi(f1.w)));
            *(uint4*)(sm + nxt + a_of[3]) = make_uint4(
                pack2(f2.x - trunc_hi(f2.x), f2.y - trunc_hi(f2.y)),
                pack2(f2.z - trunc_hi(f2.z), f2.w - trunc_hi(f2.w)),
                pack2(f3.x - trunc_hi(f3.x), f3.y - trunc_hi(f3.y)),
                pack2(f3.z - trunc_hi(f3.z), f3.w - trunc_hi(f3.w)));
            CP_WAIT0();
        }
        __syncthreads();
    }

    // epilogue: bias add, write g_h, fused column sum/sumsq
    const int erow = lane >> 2;
    const int ecol = (lane & 3) * 2;
    float* ss = (float*)sm;
    float* qq = (float*)(sm + 2048);
    #pragma unroll
    for (int nt = 0; nt < 8; ++nt) {
        int lc = n0w + nt * 8 + ecol;
        int gc = n0 + lc;
        float bx = sbias[lc], by = sbias[lc + 1];
        float sx = 0.f, sy = 0.f, qx = 0.f, qy = 0.f;
        #pragma unroll
        for (int mt = 0; mt < 2; ++mt) {
            int gr0 = row0 + m0w + mt * 16 + erow;
            float2 v0 = make_float2(acc[mt][nt][0] + bx, acc[mt][nt][1] + by);
            float2 v1 = make_float2(acc[mt][nt][2] + bx, acc[mt][nt][3] + by);
            *(float2*)&g_h[(size_t)gr0 * DHID + gc]       = v0;
            *(float2*)&g_h[(size_t)(gr0 + 8) * DHID + gc] = v1;
            sx += v0.x + v1.x;  sy += v0.y + v1.y;
            qx = fmaf(v0.x, v0.x, fmaf(v1.x, v1.x, qx));
            qy = fmaf(v0.y, v0.y, fmaf(v1.y, v1.y, qy));
        }
        #pragma unroll
        for (int o = 4; o < 32; o <<= 1) {
            sx += __shfl_xor_sync(0xffffffffu, sx, o);
            sy += __shfl_xor_sync(0xffffffffu, sy, o);
            qx += __shfl_xor_sync(0xffffffffu, qx, o);
            qy += __shfl_xor_sync(0xffffffffu, qy, o);
        }
        if (lane < 4) {
            int idx = ((wid * 8 + nt) * 4 + lane) * 2;
            ss[idx] = sx;  ss[idx + 1] = sy;
            qq[idx] = qx;  qq[idx + 1] = qy;
        }
    }
    __syncthreads();
    if (tid < 128) {
        const int lc = tid;
        const int hi = (lc >= 64);
        const int within = lc - hi * 64;
        const int nt  = within >> 3;
        const int grp = (within & 7) >> 1;
        const int xy  = within & 1;
        float s = 0.f, q = 0.f;
        #pragma unroll
        for (int w = 0; w < 4; ++w) {
            int wd = hi * 4 + w;
            int idx = ((wd * 8 + nt) * 4 + grp) * 2 + xy;
            s += ss[idx];
            q += qq[idx];
        }
        int cta = blockIdx.y * 2 + blockIdx.x;
        g_psum[cta * 128 + lc]   = s;
        g_psumsq[cta * 128 + lc] = q;
    }
}

// ---------------------------------------------------------------------------
// Kernel 3: finalize BN coefficients (256 blocks, tree reduce)
// ---------------------------------------------------------------------------
__global__ __launch_bounds__(256)
void stats_final_kernel(const float* __restrict__ gamma,
                        const float* __restrict__ beta, int nrows)
{
    __shared__ float rs[256], rq[256];
    const int c   = blockIdx.x;
    const int x   = c >> 7;
    const int lc  = c & 127;
    const int tid = threadIdx.x;
    float s = 0.f, q = 0.f;
    for (int y = tid; y < 2048; y += 256) {
        int cta = y * 2 + x;
        s += g_psum[cta * 128 + lc];
        q += g_psumsq[cta * 128 + lc];
    }
    rs[tid] = s; rq[tid] = q;
    __syncthreads();
    #pragma unroll
    for (int o = 128; o; o >>= 1) {
        if (tid < o) { rs[tid] += rs[tid + o]; rq[tid] += rq[tid + o]; }
        __syncthreads();
    }
    if (tid == 0) {
        float inv_n = 1.0f / (float)nrows;
        float mean  = rs[0] * inv_n;
        float var   = fmaf(-mean, mean, rq[0] * inv_n);
        float rstd  = rsqrtf(var + 1e-5f);
        float a     = gamma[c] * rstd;
        g_bn_a[c] = a;
        g_bn_c[c] = fmaf(-mean, a, beta[c]);
    }
}

// Kernel 4: scores (warp per row)
__global__ __launch_bounds__(256)
void scores_kernel(const float* __restrict__ W2, const float* __restrict__ b2,
                   int nrows)
{
    __shared__ float sa[DHID], sc[DHID], sw[DHID];
    const int tid = threadIdx.x;
    sa[tid] = g_bn_a[tid];
    sc[tid] = g_bn_c[tid];
    sw[tid] = W2[tid];
    __syncthreads();

    const int warp = tid >> 5;
    const int lane = tid & 31;
    const int row  = blockIdx.x * 8 + warp;
    if (row >= nrows) return;

    const float* hr = g_h + (size_t)row * DHID;
    float acc = 0.f;
    #pragma unroll
    for (int part = 0; part < 2; ++part) {
        int c0 = part * 128 + lane * 4;
        float4 v = *(const float4*)(hr + c0);
        acc += fmaxf(fmaf(sa[c0 + 0], v.x, sc[c0 + 0]), 0.f) * sw[c0 + 0];
        acc += fmaxf(fmaf(sa[c0 + 1], v.y, sc[c0 + 1]), 0.f) * sw[c0 + 1];
        acc += fmaxf(fmaf(sa[c0 + 2], v.z, sc[c0 + 2]), 0.f) * sw[c0 + 2];
        acc += fmaxf(fmaf(sa[c0 + 3], v.w, sc[c0 + 3]), 0.f) * sw[c0 + 3];
    }
    #pragma unroll
    for (int o = 16; o; o >>= 1) acc += __shfl_xor_sync(0xffffffffu, acc, o);
    if (lane == 0) g_scores[row] = acc + b2[0];
}

// Kernel 5: bag offsets
__global__ void offsets_kernel(const int* __restrict__ bag_sizes, int n_bags)
{
    if (threadIdx.x == 0 && blockIdx.x == 0) {
        long long a = 0;
        g_off[0] = 0;
        for (int b = 0; b < n_bags; ++b) { a += (long long)bag_sizes[b]; g_off[b + 1] = a; }
    }
}

// Kernel 6: per-bag stable softmax
__global__ __launch_bounds__(256)
void bag_softmax_kernel(float* __restrict__ out)
{
    __shared__ float red[256];
    const int b   = blockIdx.x;
    const int tid = threadIdx.x;
    const long long s = g_off[b];
    const long long e = g_off[b + 1];

    float m = NEG_INF_F;
    for (long long i = s + tid; i < e; i += 256) m = fmaxf(m, g_scores[i]);
    red[tid] = m;
    __syncthreads();
    #pragma unroll
    for (int o = 128; o; o >>= 1) {
        if (tid < o) red[tid] = fmaxf(red[tid], red[tid + o]);
        __syncthreads();
    }
    const float M = red[0];
    __syncthreads();

    float z = 0.f;
    for (long long i = s + tid; i < e; i += 256) {
        float ev = expf(g_scores[i] - M);
        out[i] = ev;
        z += ev;
    }
    red[tid] = z;
    __syncthreads();
    #pragma unroll
    for (int o = 128; o; o >>= 1) {
        if (tid < o) red[tid] += red[tid + o];
        __syncthreads();
    }
    const float inv = 1.0f / red[0];
    for (long long i = s + tid; i < e; i += 256) out[i] *= inv;
}

// ---------------------------------------------------------------------------
extern "C" void kernel_launch(void* const* d_in, const int* in_sizes, int n_in,
                              void* d_out, int out_size)
{
    const float* features  = (const float*)d_in[0];
    const int*   bag_sizes = (const int*)d_in[1];
    const float* W1        = (const float*)d_in[2];
    const float* b1        = (const float*)d_in[3];
    const float* gamma     = (const float*)d_in[4];
    const float* beta      = (const float*)d_in[5];
    const float* W2        = (const float*)d_in[6];
    const float* b2        = (const float*)d_in[7];
    float*       out       = (float*)d_out;

    const int n      = out_size;        // 262144
    const int n_bags = in_sizes[1];     // 128

    const int GEMM_SMEM = 65536;
    cudaFuncSetAttribute(gemm_mma_kernel,
                         cudaFuncAttributeMaxDynamicSharedMemorySize, GEMM_SMEM);

    convert_w1_kernel<<<DHID, 256>>>(W1);
    dim3 ggrid(2, n / 128);
    gemm_mma_kernel<<<ggrid, 256, GEMM_SMEM>>>(features, b1, n);
    stats_final_kernel<<<DHID, 256>>>(gamma, beta, n);
    scores_kernel<<<(n + 7) / 8, 256>>>(W2, b2, n);
    offsets_kernel<<<1, 1>>>(bag_sizes, n_bags);
    bag_softmax_kernel<<<n_bags, 256>>>(out);
}